// round 7
// baseline (speedup 1.0000x reference)
#include <cuda_runtime.h>
#include <cuda_bf16.h>
#include <cstdint>

#define BT 6
#define NN 4096
#define DD 64
#define WC 8192

typedef unsigned long long u64;

// Scratch (device globals — no allocations allowed)
__device__ float    g_mii [BT*NN];           // ||e_row||^2 (softmax shift)
__device__ uint32_t g_Eh32[BT*NN*32];        // E hi, bf16x2 packed (32 u32/row)
__device__ uint32_t g_El32[BT*NN*32];        // E lo
__device__ uint32_t g_Xth [BT*DD*(NN/2)];    // X^T hi: [bt*64+d][k/2] bf16x2
__device__ uint32_t g_Xtl [BT*DD*(NN/2)];    // X^T lo
__device__ float    g_W   [(size_t)NN*WC];   // hypernet weights, 134 MB
__device__ float    g_xg2 [BT*NN*DD];        // attention output (normalized)
__device__ float    g_bias[BT*DD];

// ---------------- helpers ----------------
#define FMA2(d, a, b, c) asm("fma.rn.f32x2 %0, %1, %2, %3;" : "=l"(d) : "l"(a), "l"(b), "l"(c))
__device__ __forceinline__ u64 dup2(float v) {
    u64 r; asm("mov.b64 %0, {%1, %1};" : "=l"(r) : "f"(v)); return r;
}
__device__ __forceinline__ u64 pack2(float a, float b) {
    u64 r; asm("mov.b64 %0, {%1, %2};" : "=l"(r) : "f"(a), "f"(b)); return r;
}
__device__ __forceinline__ float2 unpack2(u64 v) {
    float a, b; asm("mov.b64 {%0, %1}, %2;" : "=f"(a), "=f"(b) : "l"(v));
    return make_float2(a, b);
}
__device__ __forceinline__ uint32_t pkbf(float a, float b) {
    __nv_bfloat162 t; t.x = __float2bfloat16(a); t.y = __float2bfloat16(b);
    return *reinterpret_cast<uint32_t*>(&t);
}
__device__ __forceinline__ void split2(float a, float b, uint32_t& hi, uint32_t& lo) {
    __nv_bfloat16 ha = __float2bfloat16(a), hb = __float2bfloat16(b);
    __nv_bfloat162 hp; hp.x = ha; hp.y = hb;
    hi = *reinterpret_cast<uint32_t*>(&hp);
    lo = pkbf(a - __bfloat162float(ha), b - __bfloat162float(hb));
}
__device__ __forceinline__ void mma16816(float* c, const uint32_t* a, uint32_t b0, uint32_t b1) {
    asm volatile(
        "mma.sync.aligned.m16n8k16.row.col.f32.bf16.bf16.f32 "
        "{%0,%1,%2,%3}, {%4,%5,%6,%7}, {%8,%9}, {%0,%1,%2,%3};"
        : "+f"(c[0]), "+f"(c[1]), "+f"(c[2]), "+f"(c[3])
        : "r"(a[0]), "r"(a[1]), "r"(a[2]), "r"(a[3]), "r"(b0), "r"(b1));
}
__device__ __forceinline__ void cpa16(void* dst, const void* src) {
    uint32_t d = (uint32_t)__cvta_generic_to_shared(dst);
    asm volatile("cp.async.ca.shared.global [%0], [%1], 16;" :: "r"(d), "l"(src));
}
#define CP_COMMIT() asm volatile("cp.async.commit_group;" ::: "memory")
#define CP_WAIT1()  asm volatile("cp.async.wait_group 1;" ::: "memory")

// ---------------- K1: LayerNorm -> bf16 hi/lo + mii ----------------
__global__ __launch_bounds__(256) void k_ln(
    const float* __restrict__ ne, const float* __restrict__ te,
    const float* __restrict__ gamma, const float* __restrict__ beta)
{
    int row = blockIdx.x * 8 + (threadIdx.x >> 5);
    int lane = threadIdx.x & 31;
    int bt = row >> 12, n = row & (NN - 1);
    float2 nv = *(const float2*)(ne + n * DD + 2 * lane);
    float2 tv = *(const float2*)(te + bt * DD + 2 * lane);
    float e0 = nv.x + tv.x, e1 = nv.y + tv.y;
    float s = e0 + e1, s2 = e0 * e0 + e1 * e1;
    #pragma unroll
    for (int o = 16; o; o >>= 1) {
        s  += __shfl_xor_sync(~0u, s,  o);
        s2 += __shfl_xor_sync(~0u, s2, o);
    }
    float mu = s * (1.f / 64.f), var = s2 * (1.f / 64.f) - mu * mu;
    float rs = rsqrtf(var + 1e-12f);
    float o0 = (e0 - mu) * rs * gamma[2 * lane]     + beta[2 * lane];
    float o1 = (e1 - mu) * rs * gamma[2 * lane + 1] + beta[2 * lane + 1];
    uint32_t hi, lo;
    split2(o0, o1, hi, lo);
    g_Eh32[row * 32 + lane] = hi;
    g_El32[row * 32 + lane] = lo;
    float q2 = o0 * o0 + o1 * o1;
    #pragma unroll
    for (int o = 16; o; o >>= 1) q2 += __shfl_xor_sync(~0u, q2, o);
    if (lane == 0) g_mii[row] = q2;
}

// ---------------- K1b: X -> X^T bf16 hi/lo ----------------
__global__ __launch_bounds__(256) void k_xsplit(const float* __restrict__ x)
{
    __shared__ float t[64][65];
    int bt = blockIdx.y, k0 = blockIdx.x * 64;
    for (int i = threadIdx.x; i < 4096; i += 256)
        t[i >> 6][i & 63] = x[((size_t)bt * NN + k0 + (i >> 6)) * DD + (i & 63)];
    __syncthreads();
    for (int i = threadIdx.x; i < 2048; i += 256) {
        int d = i >> 5, c2 = i & 31;
        uint32_t hi, lo;
        split2(t[c2 * 2][d], t[c2 * 2 + 1][d], hi, lo);
        size_t gi = (size_t)(bt * DD + d) * (NN / 2) + k0 / 2 + c2;
        g_Xth[gi] = hi;
        g_Xtl[gi] = lo;
    }
}

// ---------------- K2: bias ----------------
__global__ void k_bias(const float* __restrict__ te, const float* __restrict__ bp)
{
    int bt = blockIdx.x, o = threadIdx.x;
    float s = 0.f;
    #pragma unroll
    for (int d = 0; d < DD; d++) s += te[bt * DD + d] * bp[d * DD + o];
    g_bias[bt * DD + o] = s;
}

// ---------------- K3: W = node_emb @ weights_pool  (128x128 tile, 8x8 f32x2)
__global__ __launch_bounds__(256) void k_wgemm(
    const float* __restrict__ A, const float* __restrict__ Bm)
{
    __shared__ float As[64][128];    // [k][n]
    __shared__ float Bs[64][128];    // [k][c]
    int n0 = blockIdx.y * 128, c0 = blockIdx.x * 128, tid = threadIdx.x;

    // A tile (128n x 64k), transposed store
    #pragma unroll
    for (int p = 0; p < 8; p++) {
        int idx = p * 256 + tid, r = idx >> 4, c4 = idx & 15;
        float4 v = ((const float4*)A)[(size_t)(n0 + r) * 16 + c4];
        As[c4 * 4 + 0][r] = v.x; As[c4 * 4 + 1][r] = v.y;
        As[c4 * 4 + 2][r] = v.z; As[c4 * 4 + 3][r] = v.w;
    }
    // B tile (64k x 128c)
    #pragma unroll
    for (int p = 0; p < 8; p++) {
        int idx = p * 256 + tid, r = idx >> 5, c4 = idx & 31;
        *(float4*)&Bs[r][c4 * 4] = *(const float4*)(Bm + (size_t)r * WC + c0 + c4 * 4);
    }
    __syncthreads();

    int tx = tid & 15, ty = tid >> 4;     // 8c, 8n each
    u64 acc[8][4];
    #pragma unroll
    for (int i = 0; i < 8; i++)
        #pragma unroll
        for (int j = 0; j < 4; j++) acc[i][j] = 0ull;

    #pragma unroll
    for (int k = 0; k < 64; k++) {
        float a[8];
        *(float4*)&a[0] = *(const float4*)&As[k][ty * 8];
        *(float4*)&a[4] = *(const float4*)&As[k][ty * 8 + 4];
        ulonglong2 b01 = *(const ulonglong2*)&Bs[k][tx * 8];
        ulonglong2 b23 = *(const ulonglong2*)&Bs[k][tx * 8 + 4];
        #pragma unroll
        for (int i = 0; i < 8; i++) {
            u64 ai = dup2(a[i]);
            FMA2(acc[i][0], ai, b01.x, acc[i][0]);
            FMA2(acc[i][1], ai, b01.y, acc[i][1]);
            FMA2(acc[i][2], ai, b23.x, acc[i][2]);
            FMA2(acc[i][3], ai, b23.y, acc[i][3]);
        }
    }
    #pragma unroll
    for (int i = 0; i < 8; i++) {
        float2 v0 = unpack2(acc[i][0]), v1 = unpack2(acc[i][1]);
        float2 v2 = unpack2(acc[i][2]), v3 = unpack2(acc[i][3]);
        float* wp = g_W + (size_t)(n0 + ty * 8 + i) * WC + c0 + tx * 8;
        *(float4*)wp       = make_float4(v0.x, v0.y, v1.x, v1.y);
        *(float4*)(wp + 4) = make_float4(v2.x, v2.y, v3.x, v3.y);
    }
}

// ---------------- K4: HMMA attention (bf16 hi/lo split, 3 passes) ----------
__global__ __launch_bounds__(128) void k_attn_mma()
{
    __shared__ uint32_t sEh[2][32][36], sEl[2][32][36];
    __shared__ uint32_t sXh[2][64][20], sXl[2][64][20];

    const int tid = threadIdx.x, w = tid >> 5, l = tid & 31;
    const int tig = l & 3, gr = l >> 2;
    const int bt = blockIdx.y;
    const int q0 = blockIdx.x * 64;

    const size_t qrow = (size_t)(bt * NN + q0 + w * 16 + gr);
    uint32_t Qh[4][4], Ql[4][4];
    #pragma unroll
    for (int kc = 0; kc < 4; kc++) {
        int c0 = kc * 8 + tig, c1 = kc * 8 + 4 + tig;
        Qh[kc][0] = g_Eh32[qrow * 32 + c0];
        Qh[kc][1] = g_Eh32[(qrow + 8) * 32 + c0];
        Qh[kc][2] = g_Eh32[qrow * 32 + c1];
        Qh[kc][3] = g_Eh32[(qrow + 8) * 32 + c1];
        Ql[kc][0] = g_El32[qrow * 32 + c0];
        Ql[kc][1] = g_El32[(qrow + 8) * 32 + c0];
        Ql[kc][2] = g_El32[qrow * 32 + c1];
        Ql[kc][3] = g_El32[(qrow + 8) * 32 + c1];
    }
    const float mii0 = g_mii[qrow];
    const float mii1 = g_mii[qrow + 8];

    float acc[8][4];
    #pragma unroll
    for (int i = 0; i < 8; i++)
        #pragma unroll
        for (int j = 0; j < 4; j++) acc[i][j] = 0.f;
    float den0 = 0.f, den1 = 0.f;

    auto prefetch = [&](int t) {
        if (t < 128) {
            int b = t & 1, m = t * 32;
            #pragma unroll
            for (int i = tid; i < 256; i += 128) {
                int r = i >> 3, c = (i & 7) << 2;
                size_t g = (size_t)(bt * NN + m + r) * 32 + c;
                cpa16(&sEh[b][r][c], g_Eh32 + g);
                cpa16(&sEl[b][r][c], g_El32 + g);
            }
            #pragma unroll
            for (int i = tid; i < 256; i += 128) {
                int r = i >> 2, c = (i & 3) << 2;
                size_t g = (size_t)(bt * DD + r) * (NN / 2) + (m >> 1) + c;
                cpa16(&sXh[b][r][c], g_Xth + g);
                cpa16(&sXl[b][r][c], g_Xtl + g);
            }
        }
        CP_COMMIT();
    };

    prefetch(0);

    for (int t = 0; t < 128; t++) {
        prefetch(t + 1);
        CP_WAIT1();
        __syncthreads();

        const uint32_t (*Eh)[36] = sEh[t & 1];
        const uint32_t (*El)[36] = sEl[t & 1];
        const uint32_t (*Xh)[20] = sXh[t & 1];
        const uint32_t (*Xl)[20] = sXl[t & 1];

        float sacc[4][4];
        #pragma unroll
        for (int i = 0; i < 4; i++)
            #pragma unroll
            for (int j = 0; j < 4; j++) sacc[i][j] = 0.f;
        #pragma unroll
        for (int kc = 0; kc < 4; kc++) {
            #pragma unroll
            for (int nt = 0; nt < 4; nt++) {
                const uint32_t* er = Eh[nt * 8 + gr];
                const uint32_t* lr = El[nt * 8 + gr];
                uint32_t bh0 = er[kc * 8 + tig], bh1 = er[kc * 8 + 4 + tig];
                uint32_t bl0 = lr[kc * 8 + tig], bl1 = lr[kc * 8 + 4 + tig];
                mma16816(sacc[nt], Qh[kc], bh0, bh1);
                mma16816(sacc[nt], Qh[kc], bl0, bl1);
                mma16816(sacc[nt], Ql[kc], bh0, bh1);
            }
        }

        uint32_t ph[2][4], pl[2][4];
        #pragma unroll
        for (int nt = 0; nt < 4; nt++) {
            float p0 = __expf(sacc[nt][0] - mii0);
            float p1 = __expf(sacc[nt][1] - mii0);
            float p2 = __expf(sacc[nt][2] - mii1);
            float p3 = __expf(sacc[nt][3] - mii1);
            den0 += p0 + p1;
            den1 += p2 + p3;
            uint32_t h01, l01, h23, l23;
            split2(p0, p1, h01, l01);
            split2(p2, p3, h23, l23);
            int kc2 = nt >> 1;
            if ((nt & 1) == 0) {
                ph[kc2][0] = h01; ph[kc2][1] = h23;
                pl[kc2][0] = l01; pl[kc2][1] = l23;
            } else {
                ph[kc2][2] = h01; ph[kc2][3] = h23;
                pl[kc2][2] = l01; pl[kc2][3] = l23;
            }
        }

        #pragma unroll
        for (int kc2 = 0; kc2 < 2; kc2++) {
            #pragma unroll
            for (int dt = 0; dt < 8; dt++) {
                const uint32_t* xr = Xh[dt * 8 + gr];
                const uint32_t* yr = Xl[dt * 8 + gr];
                uint32_t bh0 = xr[kc2 * 8 + tig], bh1 = xr[kc2 * 8 + 4 + tig];
                uint32_t bl0 = yr[kc2 * 8 + tig], bl1 = yr[kc2 * 8 + 4 + tig];
                mma16816(acc[dt], ph[kc2], bh0, bh1);
                mma16816(acc[dt], ph[kc2], bl0, bl1);
                mma16816(acc[dt], pl[kc2], bh0, bh1);
            }
        }
        __syncthreads();
    }

    den0 += __shfl_xor_sync(~0u, den0, 1);
    den0 += __shfl_xor_sync(~0u, den0, 2);
    den1 += __shfl_xor_sync(~0u, den1, 1);
    den1 += __shfl_xor_sync(~0u, den1, 2);
    float i0 = 1.f / den0, i1 = 1.f / den1;
    #pragma unroll
    for (int dt = 0; dt < 8; dt++) {
        *(float2*)(g_xg2 + qrow * 64 + dt * 8 + 2 * tig) =
            make_float2(acc[dt][0] * i0, acc[dt][1] * i0);
        *(float2*)(g_xg2 + (qrow + 8) * 64 + dt * 8 + 2 * tig) =
            make_float2(acc[dt][2] * i1, acc[dt][3] * i1);
    }
}

// ---------------- K5: apply hypernet weights (v3: W read once per element) --
// 128 threads = 64 o x 2 k-halves. All 6 bt accumulated in registers as
// 3 f32x2 pairs. Ws[ki*64+o] stride-64 walk is bank-conflict-free.
__global__ __launch_bounds__(128) void k_apply(const float* __restrict__ x,
                                               float* __restrict__ out)
{
    __shared__ float Ws[WC];         // 32 KB, natural [ki*64+o]
    __shared__ u64   xgp[3][128];    // bt-pair packed x_g: [btp][ki]
    __shared__ float red[6][64];     // cross-kh reduction
    const int tid = threadIdx.x;
    const int n = blockIdx.x;

    const float4* Wn = (const float4*)(g_W + (size_t)n * WC);
    #pragma unroll
    for (int i = tid; i < WC / 4; i += 128) ((float4*)Ws)[i] = Wn[i];
    for (int i = tid; i < 3 * 128; i += 128) {
        int btp = i >> 7, ki = i & 127;
        const float* src = (ki < 64) ? x : g_xg2;
        int c = ki & 63;
        float v0 = src[((size_t)(2 * btp)     * NN + n) * DD + c];
        float v1 = src[((size_t)(2 * btp + 1) * NN + n) * DD + c];
        xgp[btp][ki] = pack2(v0, v1);
    }
    __syncthreads();

    const int o = tid & 63, kh = tid >> 6;
    u64 acc[3] = {0ull, 0ull, 0ull};
    #pragma unroll
    for (int j = 0; j < 64; j++) {
        int ki = kh * 64 + j;
        u64 w2 = dup2(Ws[ki * 64 + o]);
        FMA2(acc[0], w2, xgp[0][ki], acc[0]);
        FMA2(acc[1], w2, xgp[1][ki], acc[1]);
        FMA2(acc[2], w2, xgp[2][ki], acc[2]);
    }

    if (kh == 1) {
        #pragma unroll
        for (int btp = 0; btp < 3; btp++) {
            float2 v = unpack2(acc[btp]);
            red[2 * btp][o]     = v.x;
            red[2 * btp + 1][o] = v.y;
        }
    }
    __syncthreads();
    if (kh == 0) {
        #pragma unroll
        for (int btp = 0; btp < 3; btp++) {
            float2 v = unpack2(acc[btp]);
            int b0 = 2 * btp, b1 = 2 * btp + 1;
            out[((size_t)b0 * NN + n) * DD + o] = v.x + red[b0][o] + g_bias[b0 * DD + o];
            out[((size_t)b1 * NN + n) * DD + o] = v.y + red[b1][o] + g_bias[b1 * DD + o];
        }
    }
}

// ---------------------------------------------------------------------------
extern "C" void kernel_launch(void* const* d_in, const int* in_sizes, int n_in,
                              void* d_out, int out_size)
{
    const float* x     = (const float*)d_in[0];
    const float* ne    = (const float*)d_in[1];
    const float* te    = (const float*)d_in[2];
    const float* wpool = (const float*)d_in[3];
    const float* bpool = (const float*)d_in[4];
    const float* gamma = (const float*)d_in[5];
    const float* beta  = (const float*)d_in[6];
    float* out = (float*)d_out;

    k_ln      <<<(BT * NN) / 8, 256>>>(ne, te, gamma, beta);
    k_xsplit  <<<dim3(NN / 64, BT), 256>>>(x);
    k_bias    <<<BT, DD>>>(te, bpool);
    k_wgemm   <<<dim3(WC / 128, NN / 128), 256>>>(ne, wpool);
    k_attn_mma<<<dim3(NN / 64, BT), 128>>>();
    k_apply   <<<NN, 128>>>(x, out);
}

// round 8
// speedup vs baseline: 1.6167x; 1.6167x over previous
#include <cuda_runtime.h>
#include <cuda_bf16.h>
#include <cstdint>

#define BT 6
#define NN 4096
#define DD 64
#define WC 8192

typedef unsigned long long u64;

// Scratch (device globals — no allocations allowed)
__device__ float    g_mii [BT*NN];
__device__ uint32_t g_Eh32[BT*NN*32];        // E hi (bf16x2 along d)
__device__ uint32_t g_El32[BT*NN*32];        // E lo
__device__ uint32_t g_Xth [BT*DD*(NN/2)];    // X^T hi: [bt*64+d][k/2]
__device__ uint32_t g_Xtl [BT*DD*(NN/2)];    // X^T lo
__device__ uint32_t g_Ah  [NN*32];           // node_emb hi (bf16x2 along d)
__device__ uint32_t g_Al  [NN*32];           // node_emb lo
__device__ uint32_t g_Bph [WC*32];           // wpool^T hi: [c][d/2]
__device__ uint32_t g_Bpl [WC*32];           // wpool^T lo
__device__ float    g_W   [(size_t)NN*WC];   // hypernet weights, 134 MB
__device__ float    g_xg2 [BT*NN*DD];
__device__ float    g_bias[BT*DD];

// ---------------- helpers ----------------
__device__ __forceinline__ uint32_t pkbf(float a, float b) {
    __nv_bfloat162 t; t.x = __float2bfloat16(a); t.y = __float2bfloat16(b);
    return *reinterpret_cast<uint32_t*>(&t);
}
__device__ __forceinline__ void split2(float a, float b, uint32_t& hi, uint32_t& lo) {
    __nv_bfloat16 ha = __float2bfloat16(a), hb = __float2bfloat16(b);
    __nv_bfloat162 hp; hp.x = ha; hp.y = hb;
    hi = *reinterpret_cast<uint32_t*>(&hp);
    lo = pkbf(a - __bfloat162float(ha), b - __bfloat162float(hb));
}
__device__ __forceinline__ void mma16816(float* c, const uint32_t* a, uint32_t b0, uint32_t b1) {
    asm volatile(
        "mma.sync.aligned.m16n8k16.row.col.f32.bf16.bf16.f32 "
        "{%0,%1,%2,%3}, {%4,%5,%6,%7}, {%8,%9}, {%0,%1,%2,%3};"
        : "+f"(c[0]), "+f"(c[1]), "+f"(c[2]), "+f"(c[3])
        : "r"(a[0]), "r"(a[1]), "r"(a[2]), "r"(a[3]), "r"(b0), "r"(b1));
}
__device__ __forceinline__ void cpa16(void* dst, const void* src) {
    uint32_t d = (uint32_t)__cvta_generic_to_shared(dst);
    asm volatile("cp.async.ca.shared.global [%0], [%1], 16;" :: "r"(d), "l"(src));
}
#define CP_COMMIT() asm volatile("cp.async.commit_group;" ::: "memory")
#define CP_WAIT1()  asm volatile("cp.async.wait_group 1;" ::: "memory")

// ---------------- K1: LayerNorm -> bf16 hi/lo + mii ----------------
__global__ __launch_bounds__(256) void k_ln(
    const float* __restrict__ ne, const float* __restrict__ te,
    const float* __restrict__ gamma, const float* __restrict__ beta)
{
    int row = blockIdx.x * 8 + (threadIdx.x >> 5);
    int lane = threadIdx.x & 31;
    int bt = row >> 12, n = row & (NN - 1);
    float2 nv = *(const float2*)(ne + n * DD + 2 * lane);
    float2 tv = *(const float2*)(te + bt * DD + 2 * lane);
    float e0 = nv.x + tv.x, e1 = nv.y + tv.y;
    float s = e0 + e1, s2 = e0 * e0 + e1 * e1;
    #pragma unroll
    for (int o = 16; o; o >>= 1) {
        s  += __shfl_xor_sync(~0u, s,  o);
        s2 += __shfl_xor_sync(~0u, s2, o);
    }
    float mu = s * (1.f / 64.f), var = s2 * (1.f / 64.f) - mu * mu;
    float rs = rsqrtf(var + 1e-12f);
    float o0 = (e0 - mu) * rs * gamma[2 * lane]     + beta[2 * lane];
    float o1 = (e1 - mu) * rs * gamma[2 * lane + 1] + beta[2 * lane + 1];
    uint32_t hi, lo;
    split2(o0, o1, hi, lo);
    g_Eh32[row * 32 + lane] = hi;
    g_El32[row * 32 + lane] = lo;
    float q2 = o0 * o0 + o1 * o1;
    #pragma unroll
    for (int o = 16; o; o >>= 1) q2 += __shfl_xor_sync(~0u, q2, o);
    if (lane == 0) g_mii[row] = q2;
}

// ---------------- K1b: X -> X^T bf16 hi/lo ----------------
__global__ __launch_bounds__(256) void k_xsplit(const float* __restrict__ x)
{
    __shared__ float t[64][65];
    int bt = blockIdx.y, k0 = blockIdx.x * 64;
    for (int i = threadIdx.x; i < 4096; i += 256)
        t[i >> 6][i & 63] = x[((size_t)bt * NN + k0 + (i >> 6)) * DD + (i & 63)];
    __syncthreads();
    for (int i = threadIdx.x; i < 2048; i += 256) {
        int d = i >> 5, c2 = i & 31;
        uint32_t hi, lo;
        split2(t[c2 * 2][d], t[c2 * 2 + 1][d], hi, lo);
        size_t gi = (size_t)(bt * DD + d) * (NN / 2) + k0 / 2 + c2;
        g_Xth[gi] = hi;
        g_Xtl[gi] = lo;
    }
}

// ---------------- K1c: node_emb -> bf16 hi/lo (row-major) ----------------
__global__ __launch_bounds__(256) void k_nesplit(const float* __restrict__ ne)
{
    int row = blockIdx.x * 8 + (threadIdx.x >> 5);
    int lane = threadIdx.x & 31;
    float2 v = *(const float2*)(ne + row * DD + 2 * lane);
    uint32_t hi, lo;
    split2(v.x, v.y, hi, lo);
    g_Ah[row * 32 + lane] = hi;
    g_Al[row * 32 + lane] = lo;
}

// ---------------- K1d: wpool [64][8192] -> transposed bf16 hi/lo [c][d/2] ---
__global__ __launch_bounds__(256) void k_wpsplit(const float* __restrict__ wp)
{
    __shared__ float t[64][65];
    int c0 = blockIdx.x * 64;
    for (int i = threadIdx.x; i < 4096; i += 256)
        t[i >> 6][i & 63] = wp[(size_t)(i >> 6) * WC + c0 + (i & 63)];
    __syncthreads();
    for (int i = threadIdx.x; i < 2048; i += 256) {
        int c = i >> 5, dp = i & 31;
        uint32_t hi, lo;
        split2(t[dp * 2][c], t[dp * 2 + 1][c], hi, lo);
        g_Bph[(size_t)(c0 + c) * 32 + dp] = hi;
        g_Bpl[(size_t)(c0 + c) * 32 + dp] = lo;
    }
}

// ---------------- K2: bias ----------------
__global__ void k_bias(const float* __restrict__ te, const float* __restrict__ bp)
{
    int bt = blockIdx.x, o = threadIdx.x;
    float s = 0.f;
    #pragma unroll
    for (int d = 0; d < DD; d++) s += te[bt * DD + d] * bp[d * DD + o];
    g_bias[bt * DD + o] = s;
}

// ---------------- K3: W = node_emb @ wpool via HMMA (hi/lo 3-pass) ----------
// Block: 128n x 128c, 8 warps, warp = 16n x 128c. K=64 (no k-loop).
__global__ __launch_bounds__(256) void k_wgemm_mma()
{
    __shared__ uint32_t sBh[128][36], sBl[128][36];
    const int tid = threadIdx.x, w = tid >> 5, l = tid & 31;
    const int gr = l >> 2, tig = l & 3;
    const int n0 = blockIdx.y * 128, c0 = blockIdx.x * 128;

    for (int i = tid; i < 4096; i += 256) {
        int c = i >> 5, dp = i & 31;
        sBh[c][dp] = g_Bph[(size_t)(c0 + c) * 32 + dp];
        sBl[c][dp] = g_Bpl[(size_t)(c0 + c) * 32 + dp];
    }

    const size_t ar = (size_t)(n0 + w * 16 + gr);
    uint32_t Ahf[4][4], Alf[4][4];
    #pragma unroll
    for (int kc = 0; kc < 4; kc++) {
        int p0 = kc * 8 + tig, p1 = kc * 8 + 4 + tig;
        Ahf[kc][0] = g_Ah[ar * 32 + p0];
        Ahf[kc][1] = g_Ah[(ar + 8) * 32 + p0];
        Ahf[kc][2] = g_Ah[ar * 32 + p1];
        Ahf[kc][3] = g_Ah[(ar + 8) * 32 + p1];
        Alf[kc][0] = g_Al[ar * 32 + p0];
        Alf[kc][1] = g_Al[(ar + 8) * 32 + p0];
        Alf[kc][2] = g_Al[ar * 32 + p1];
        Alf[kc][3] = g_Al[(ar + 8) * 32 + p1];
    }
    __syncthreads();

    float acc[16][4];
    #pragma unroll
    for (int i = 0; i < 16; i++)
        #pragma unroll
        for (int j = 0; j < 4; j++) acc[i][j] = 0.f;

    #pragma unroll
    for (int ct = 0; ct < 16; ct++) {
        const uint32_t* bh = sBh[ct * 8 + gr];
        const uint32_t* bl = sBl[ct * 8 + gr];
        #pragma unroll
        for (int kc = 0; kc < 4; kc++) {
            uint32_t bh0 = bh[kc * 8 + tig], bh1 = bh[kc * 8 + 4 + tig];
            uint32_t bl0 = bl[kc * 8 + tig], bl1 = bl[kc * 8 + 4 + tig];
            mma16816(acc[ct], Ahf[kc], bh0, bh1);
            mma16816(acc[ct], Ahf[kc], bl0, bl1);
            mma16816(acc[ct], Alf[kc], bh0, bh1);
        }
    }

    #pragma unroll
    for (int ct = 0; ct < 16; ct++) {
        float* p = g_W + ar * WC + c0 + ct * 8 + 2 * tig;
        *(float2*)p            = make_float2(acc[ct][0], acc[ct][1]);
        *(float2*)(p + 8 * WC) = make_float2(acc[ct][2], acc[ct][3]);
    }
}

// ---------------- K4: HMMA attention (bf16 hi/lo split, 3 passes) ----------
__global__ __launch_bounds__(128) void k_attn_mma()
{
    __shared__ uint32_t sEh[2][32][36], sEl[2][32][36];
    __shared__ uint32_t sXh[2][64][20], sXl[2][64][20];

    const int tid = threadIdx.x, w = tid >> 5, l = tid & 31;
    const int tig = l & 3, gr = l >> 2;
    const int bt = blockIdx.y;
    const int q0 = blockIdx.x * 64;

    const size_t qrow = (size_t)(bt * NN + q0 + w * 16 + gr);
    uint32_t Qh[4][4], Ql[4][4];
    #pragma unroll
    for (int kc = 0; kc < 4; kc++) {
        int c0 = kc * 8 + tig, c1 = kc * 8 + 4 + tig;
        Qh[kc][0] = g_Eh32[qrow * 32 + c0];
        Qh[kc][1] = g_Eh32[(qrow + 8) * 32 + c0];
        Qh[kc][2] = g_Eh32[qrow * 32 + c1];
        Qh[kc][3] = g_Eh32[(qrow + 8) * 32 + c1];
        Ql[kc][0] = g_El32[qrow * 32 + c0];
        Ql[kc][1] = g_El32[(qrow + 8) * 32 + c0];
        Ql[kc][2] = g_El32[qrow * 32 + c1];
        Ql[kc][3] = g_El32[(qrow + 8) * 32 + c1];
    }
    const float mii0 = g_mii[qrow];
    const float mii1 = g_mii[qrow + 8];

    float acc[8][4];
    #pragma unroll
    for (int i = 0; i < 8; i++)
        #pragma unroll
        for (int j = 0; j < 4; j++) acc[i][j] = 0.f;
    float den0 = 0.f, den1 = 0.f;

    auto prefetch = [&](int t) {
        if (t < 128) {
            int b = t & 1, m = t * 32;
            #pragma unroll
            for (int i = tid; i < 256; i += 128) {
                int r = i >> 3, c = (i & 7) << 2;
                size_t g = (size_t)(bt * NN + m + r) * 32 + c;
                cpa16(&sEh[b][r][c], g_Eh32 + g);
                cpa16(&sEl[b][r][c], g_El32 + g);
            }
            #pragma unroll
            for (int i = tid; i < 256; i += 128) {
                int r = i >> 2, c = (i & 3) << 2;
                size_t g = (size_t)(bt * DD + r) * (NN / 2) + (m >> 1) + c;
                cpa16(&sXh[b][r][c], g_Xth + g);
                cpa16(&sXl[b][r][c], g_Xtl + g);
            }
        }
        CP_COMMIT();
    };

    prefetch(0);

    for (int t = 0; t < 128; t++) {
        prefetch(t + 1);
        CP_WAIT1();
        __syncthreads();

        const uint32_t (*Eh)[36] = sEh[t & 1];
        const uint32_t (*El)[36] = sEl[t & 1];
        const uint32_t (*Xh)[20] = sXh[t & 1];
        const uint32_t (*Xl)[20] = sXl[t & 1];

        float sacc[4][4];
        #pragma unroll
        for (int i = 0; i < 4; i++)
            #pragma unroll
            for (int j = 0; j < 4; j++) sacc[i][j] = 0.f;
        #pragma unroll
        for (int kc = 0; kc < 4; kc++) {
            #pragma unroll
            for (int nt = 0; nt < 4; nt++) {
                const uint32_t* er = Eh[nt * 8 + gr];
                const uint32_t* lr = El[nt * 8 + gr];
                uint32_t bh0 = er[kc * 8 + tig], bh1 = er[kc * 8 + 4 + tig];
                uint32_t bl0 = lr[kc * 8 + tig], bl1 = lr[kc * 8 + 4 + tig];
                mma16816(sacc[nt], Qh[kc], bh0, bh1);
                mma16816(sacc[nt], Qh[kc], bl0, bl1);
                mma16816(sacc[nt], Ql[kc], bh0, bh1);
            }
        }

        uint32_t ph[2][4], pl[2][4];
        #pragma unroll
        for (int nt = 0; nt < 4; nt++) {
            float p0 = __expf(sacc[nt][0] - mii0);
            float p1 = __expf(sacc[nt][1] - mii0);
            float p2 = __expf(sacc[nt][2] - mii1);
            float p3 = __expf(sacc[nt][3] - mii1);
            den0 += p0 + p1;
            den1 += p2 + p3;
            uint32_t h01, l01, h23, l23;
            split2(p0, p1, h01, l01);
            split2(p2, p3, h23, l23);
            int kc2 = nt >> 1;
            if ((nt & 1) == 0) {
                ph[kc2][0] = h01; ph[kc2][1] = h23;
                pl[kc2][0] = l01; pl[kc2][1] = l23;
            } else {
                ph[kc2][2] = h01; ph[kc2][3] = h23;
                pl[kc2][2] = l01; pl[kc2][3] = l23;
            }
        }

        #pragma unroll
        for (int kc2 = 0; kc2 < 2; kc2++) {
            #pragma unroll
            for (int dt = 0; dt < 8; dt++) {
                const uint32_t* xr = Xh[dt * 8 + gr];
                const uint32_t* yr = Xl[dt * 8 + gr];
                uint32_t bh0 = xr[kc2 * 8 + tig], bh1 = xr[kc2 * 8 + 4 + tig];
                uint32_t bl0 = yr[kc2 * 8 + tig], bl1 = yr[kc2 * 8 + 4 + tig];
                mma16816(acc[dt], ph[kc2], bh0, bh1);
                mma16816(acc[dt], ph[kc2], bl0, bl1);
                mma16816(acc[dt], pl[kc2], bh0, bh1);
            }
        }
        __syncthreads();
    }

    den0 += __shfl_xor_sync(~0u, den0, 1);
    den0 += __shfl_xor_sync(~0u, den0, 2);
    den1 += __shfl_xor_sync(~0u, den1, 1);
    den1 += __shfl_xor_sync(~0u, den1, 2);
    float i0 = 1.f / den0, i1 = 1.f / den1;
    #pragma unroll
    for (int dt = 0; dt < 8; dt++) {
        *(float2*)(g_xg2 + qrow * 64 + dt * 8 + 2 * tig) =
            make_float2(acc[dt][0] * i0, acc[dt][1] * i0);
        *(float2*)(g_xg2 + (qrow + 8) * 64 + dt * 8 + 2 * tig) =
            make_float2(acc[dt][2] * i1, acc[dt][3] * i1);
    }
}

// ---------------- K5: apply hypernet weights (R6-winning version) ----------
__global__ __launch_bounds__(384) void k_apply(const float* __restrict__ x,
                                               float* __restrict__ out)
{
    __shared__ float Ws[WC];
    __shared__ float xs[BT * DD];
    __shared__ float x2s[BT * DD];
    int n = blockIdx.x;
    const float4* Wn = (const float4*)(g_W + (size_t)n * WC);
    for (int i = threadIdx.x; i < WC / 4; i += 384) ((float4*)Ws)[i] = Wn[i];
    for (int i = threadIdx.x; i < BT * 16; i += 384) {
        int bt = i >> 4, c4 = i & 15;
        size_t base = ((size_t)bt * NN + n) * DD;
        ((float4*)xs)[i]  = ((const float4*)(x + base))[c4];
        ((float4*)x2s)[i] = ((const float4*)(g_xg2 + base))[c4];
    }
    __syncthreads();
    int bt = threadIdx.x / 64, o = threadIdx.x & 63;
    float s = g_bias[bt * DD + o];
    #pragma unroll
    for (int i = 0; i < DD; i++) s += xs[bt * DD + i] * Ws[i * DD + o];
    #pragma unroll
    for (int i = 0; i < DD; i++) s += x2s[bt * DD + i] * Ws[4096 + i * DD + o];
    out[((size_t)bt * NN + n) * DD + o] = s;
}

// ---------------------------------------------------------------------------
extern "C" void kernel_launch(void* const* d_in, const int* in_sizes, int n_in,
                              void* d_out, int out_size)
{
    const float* x     = (const float*)d_in[0];
    const float* ne    = (const float*)d_in[1];
    const float* te    = (const float*)d_in[2];
    const float* wpool = (const float*)d_in[3];
    const float* bpool = (const float*)d_in[4];
    const float* gamma = (const float*)d_in[5];
    const float* beta  = (const float*)d_in[6];
    float* out = (float*)d_out;

    k_ln      <<<(BT * NN) / 8, 256>>>(ne, te, gamma, beta);
    k_xsplit  <<<dim3(NN / 64, BT), 256>>>(x);
    k_nesplit <<<NN / 8, 256>>>(ne);
    k_wpsplit <<<WC / 64, 256>>>(wpool);
    k_bias    <<<BT, DD>>>(te, bpool);
    k_wgemm_mma<<<dim3(WC / 128, NN / 128), 256>>>();
    k_attn_mma<<<dim3(NN / 64, BT), 128>>>();
    k_apply   <<<NN, 384>>>(x, out);
}